// round 5
// baseline (speedup 1.0000x reference)
#include <cuda_runtime.h>
#include <math.h>

#define NTHREADS 256
#define TOPK_K   200
#define PARTS    32
#define CAND_CAP 2048

// ---------------------------------------------------------------------------
// d^2 with a fixed, non-FMA operation order so every recompute produces
// bit-identical keys (and matches XLA's unfused sum-of-squares).
__device__ __forceinline__ unsigned int key_from(
    float vx, float vy, float vz, float px, float py, float pz)
{
    float dx = __fsub_rn(vx, px);
    float dy = __fsub_rn(vy, py);
    float dz = __fsub_rn(vz, pz);
    float d2 = __fadd_rn(__fadd_rn(__fmul_rn(dx, dx), __fmul_rn(dy, dy)),
                         __fmul_rn(dz, dz));
    return __float_as_uint(d2);   // d2 >= 0, so uint order == float order
}

// Replicates the reference's per-point bin computation for rel = q_j - q_0.
__device__ __forceinline__ void process_point(
    int i, const float* __restrict__ fp,
    float q0x, float q0y, float q0z,
    unsigned int* counts)
{
    const float TWO_PI_F = 6.28318530717958647692f;
    const float PI_F     = 3.14159265358979323846f;

    float rx = __fsub_rn(fp[3 * i + 0], q0x);
    float ry = __fsub_rn(fp[3 * i + 1], q0y);
    float rz = __fsub_rn(fp[3 * i + 2], q0z);

    float axy = fmodf(atan2f(ry, rx) + TWO_PI_F, TWO_PI_F);
    float azy = fmodf(atan2f(ry, rz) + TWO_PI_F, PI_F);
    int xyb = (int)floorf(axy / (TWO_PI_F * 0.25f));
    int zyb = (int)floorf(azy / (PI_F * 0.25f));

    float d2 = __fadd_rn(__fadd_rn(__fmul_rn(rx, rx), __fmul_rn(ry, ry)),
                         __fmul_rn(rz, rz));
    float D = sqrtf(__fadd_rn(d2, 1e-7f));
    int dist = (D >= 4.0f) ? 1 : ((D >= 1.0f) ? 0 : -1);

    if (dist >= 0 && xyb >= 0 && zyb >= 0) {
        int bin = dist * 16 + xyb * 4 + zyb;
        if (bin >= 0 && bin < PARTS) atomicAdd(&counts[bin], 1u);
    }
}

// Parallel "digit where cumulative count reaches `need`" over a 256-bin
// histogram. Warp 0 computes; results broadcast via shared. Also returns the
// count inside the chosen digit (enables early exit in radix select).
__device__ __forceinline__ void find_digit(
    unsigned int* hist, int need, int t,
    unsigned int* s_digit, int* s_need, unsigned int* s_cnt)
{
    if (t < 32) {
        int base = t * 8;
        int s = 0;
        #pragma unroll
        for (int j = 0; j < 8; ++j) s += (int)hist[base + j];
        int cum = s;
        #pragma unroll
        for (int o = 1; o < 32; o <<= 1) {
            int v = __shfl_up_sync(0xFFFFFFFFu, cum, o);
            if (t >= o) cum += v;
        }
        unsigned int bal = __ballot_sync(0xFFFFFFFFu, cum >= need);
        int lane = __ffs(bal) - 1;
        if (t == lane) {
            int c = cum - s;   // exclusive prefix at this lane's first bin
            int d = base;
            while (c + (int)hist[d] < need) { c += (int)hist[d]; ++d; }
            *s_digit = (unsigned int)d;
            *s_need = need - c;
            *s_cnt = hist[d];
        }
    }
    __syncthreads();
}

__global__ __launch_bounds__(NTHREADS, 5)
void scp_topk_bins_kernel(const float* __restrict__ vp,
                          const float* __restrict__ fp,
                          float* __restrict__ out,
                          int n_fp)
{
    __shared__ unsigned int hist[256];
    __shared__ unsigned long long cand[CAND_CAP];  // (key<<32)|idx
    __shared__ unsigned int counts[PARTS];
    __shared__ unsigned long long minpack;
    __shared__ unsigned int s_cand_count;
    __shared__ unsigned int s_digit;
    __shared__ int s_need;
    __shared__ unsigned int s_cnt;
    extern __shared__ unsigned char digits[];      // one radix digit per point

    const int b = blockIdx.x;
    const int t = threadIdx.x;

    const float vx = vp[3 * b + 0];
    const float vy = vp[3 * b + 1];
    const float vz = vp[3 * b + 2];

    if (t < PARTS) counts[t] = 0;
    if (t == 0) { minpack = ~0ull; s_cand_count = 0; }
    hist[t] = 0;
    __syncthreads();

    const int ngroups = n_fp >> 2;
    const int rem = n_fp & 3;
    const int nwords = (n_fp + 3) >> 2;
    const int niterA = (ngroups + NTHREADS - 1) / NTHREADS;
    const float4* __restrict__ fp4 = (const float4*)fp;
    unsigned int* __restrict__ digw = (unsigned int*)digits;

    // ---- Pass A (only global scan): keys for 4 points/thread via 3 float4
    // loads; store digits to smem; warp-aggregated digit-0 histogram; argmin.
    unsigned long long lmin = ~0ull;
    for (int it = 0; it < niterA; ++it) {
        int g = it * NTHREADS + t;
        bool valid = (g < ngroups);
        unsigned int active = __ballot_sync(0xFFFFFFFFu, valid);
        if (valid) {
            float4 A = fp4[g * 3 + 0];
            float4 B = fp4[g * 3 + 1];
            float4 C = fp4[g * 3 + 2];
            unsigned int k0 = key_from(vx, vy, vz, A.x, A.y, A.z);
            unsigned int k1 = key_from(vx, vy, vz, A.w, B.x, B.y);
            unsigned int k2 = key_from(vx, vy, vz, B.z, B.w, C.x);
            unsigned int k3 = key_from(vx, vy, vz, C.y, C.z, C.w);
            unsigned int dpack = (k0 >> 24) | ((k1 >> 24) << 8) |
                                 ((k2 >> 24) << 16) | (k3 & 0xFF000000u);
            digw[g] = dpack;

            int base = g * 4;
            unsigned long long p;
            p = ((unsigned long long)k0 << 32) | (unsigned int)(base + 0);
            if (p < lmin) lmin = p;
            p = ((unsigned long long)k1 << 32) | (unsigned int)(base + 1);
            if (p < lmin) lmin = p;
            p = ((unsigned long long)k2 << 32) | (unsigned int)(base + 2);
            if (p < lmin) lmin = p;
            p = ((unsigned long long)k3 << 32) | (unsigned int)(base + 3);
            if (p < lmin) lmin = p;

            #pragma unroll
            for (int j = 0; j < 4; ++j) {
                unsigned int dd = (dpack >> (8 * j)) & 255u;
                unsigned int peers = __match_any_sync(active, dd);
                if ((int)(t & 31) == __ffs(peers) - 1)
                    atomicAdd(&hist[dd], (unsigned int)__popc(peers));
            }
        }
    }
    // Tail points (n_fp % 4) + pad digit bytes to the word boundary.
    if (rem) {
        bool valid = (t < rem);
        __ballot_sync(0xFFFFFFFFu, valid);
        if (valid) {
            int i = ngroups * 4 + t;
            unsigned int k = key_from(vx, vy, vz,
                                      fp[3 * i + 0], fp[3 * i + 1], fp[3 * i + 2]);
            digits[i] = (unsigned char)(k >> 24);
            atomicAdd(&hist[k >> 24], 1u);
            unsigned long long p =
                ((unsigned long long)k << 32) | (unsigned int)i;
            if (p < lmin) lmin = p;
        }
        if (t >= rem && t < 4) digits[ngroups * 4 + t] = 0xFFu;
    }
    // Warp-reduce min, then one atomic per warp.
    #pragma unroll
    for (int o = 16; o > 0; o >>= 1) {
        unsigned long long v = __shfl_xor_sync(0xFFFFFFFFu, lmin, o);
        if (v < lmin) lmin = v;
    }
    if ((t & 31) == 0) atomicMin(&minpack, lmin);
    __syncthreads();

    find_digit(hist, TOPK_K, t, &s_digit, &s_need, &s_cnt);
    const unsigned int d0 = s_digit;
    const int need = s_need;

    // Anchor = nearest fusion point (lowest index on key ties).
    const unsigned int amin = (unsigned int)(minpack & 0xFFFFFFFFull);
    const float q0x = fp[3 * amin + 0];
    const float q0y = fp[3 * amin + 1];
    const float q0z = fp[3 * amin + 2];

    // ---- Pass B: smem digit scan, SIMD byte classification.
    const unsigned int d0x4 = d0 * 0x01010101u;
    for (int w = t; w < nwords; w += NTHREADS) {
        unsigned int dw = digw[w];
        unsigned int lt = __vcmpltu4(dw, d0x4);
        unsigned int eq = __vcmpeq4(dw, d0x4);
        if (lt) {
            #pragma unroll
            for (int j = 0; j < 4; ++j)
                if ((lt >> (8 * j)) & 1u)
                    process_point(4 * w + j, fp, q0x, q0y, q0z, counts);
        }
        if (eq) {
            #pragma unroll
            for (int j = 0; j < 4; ++j)
                if ((eq >> (8 * j)) & 1u) {
                    int i = 4 * w + j;
                    if (i < n_fp) {
                        unsigned int k = key_from(vx, vy, vz,
                            fp[3 * i + 0], fp[3 * i + 1], fp[3 * i + 2]);
                        unsigned int p = atomicAdd(&s_cand_count, 1u);
                        if (p < CAND_CAP)
                            cand[p] = ((unsigned long long)k << 32) |
                                      (unsigned long long)(unsigned int)i;
                    }
                }
        }
    }
    __syncthreads();
    const unsigned int nc = s_cand_count;

    if (nc <= CAND_CAP) {
        // ---- Exact need-th smallest packed (key,idx) among candidates via
        // 8-bit radix passes with early exit. Packed ordering reproduces
        // top_k's lowest-index tie-break.
        unsigned long long prefix = (unsigned long long)d0 << 56;
        unsigned long long Pstar = prefix;
        int needc = need;
        for (int pass = 0; pass < 7; ++pass) {
            const int shift = 48 - 8 * pass;
            hist[t] = 0;
            __syncthreads();
            const unsigned long long mask = ~0ull << (shift + 8);
            for (unsigned int j = t; j < nc; j += NTHREADS) {
                unsigned long long pk = cand[j];
                if ((pk & mask) == prefix)
                    atomicAdd(&hist[(unsigned int)(pk >> shift) & 255u], 1u);
            }
            __syncthreads();
            find_digit(hist, needc, t, &s_digit, &s_need, &s_cnt);
            prefix |= (unsigned long long)s_digit << shift;
            needc = s_need;
            if ((int)s_cnt == needc) {  // whole digit taken -> cutoff known
                Pstar = prefix | ((shift > 0) ? ((1ull << shift) - 1ull) : 0ull);
                break;
            }
            if (shift == 0) Pstar = prefix;
        }
        for (unsigned int j = t; j < nc; j += NTHREADS) {
            unsigned long long pk = cand[j];
            if (pk <= Pstar)
                process_point((int)(unsigned int)(pk & 0xFFFFFFFFull),
                              fp, q0x, q0y, q0z, counts);
        }
        __syncthreads();
    } else {
        // ---- Fallback (bucket overflow, statistically never): same radix
        // select but recompute candidate keys each pass, filtered by the
        // digit array.
        unsigned long long prefix = (unsigned long long)d0 << 56;
        unsigned long long Pstar = prefix;
        int needc = need;
        for (int pass = 0; pass < 7; ++pass) {
            const int shift = 48 - 8 * pass;
            hist[t] = 0;
            __syncthreads();
            const unsigned long long mask = ~0ull << (shift + 8);
            for (int w = t; w < nwords; w += NTHREADS) {
                unsigned int eq = __vcmpeq4(digw[w], d0x4);
                if (!eq) continue;
                #pragma unroll
                for (int j = 0; j < 4; ++j)
                    if ((eq >> (8 * j)) & 1u) {
                        int i = 4 * w + j;
                        if (i < n_fp) {
                            unsigned int k = key_from(vx, vy, vz,
                                fp[3 * i + 0], fp[3 * i + 1], fp[3 * i + 2]);
                            unsigned long long pk =
                                ((unsigned long long)k << 32) |
                                (unsigned long long)(unsigned int)i;
                            if ((pk & mask) == prefix)
                                atomicAdd(
                                    &hist[(unsigned int)(pk >> shift) & 255u],
                                    1u);
                        }
                    }
            }
            __syncthreads();
            find_digit(hist, needc, t, &s_digit, &s_need, &s_cnt);
            prefix |= (unsigned long long)s_digit << shift;
            needc = s_need;
            if ((int)s_cnt == needc) {
                Pstar = prefix | ((shift > 0) ? ((1ull << shift) - 1ull) : 0ull);
                break;
            }
            if (shift == 0) Pstar = prefix;
        }
        for (int w = t; w < nwords; w += NTHREADS) {
            unsigned int eq = __vcmpeq4(digw[w], d0x4);
            if (!eq) continue;
            #pragma unroll
            for (int j = 0; j < 4; ++j)
                if ((eq >> (8 * j)) & 1u) {
                    int i = 4 * w + j;
                    if (i < n_fp) {
                        unsigned int k = key_from(vx, vy, vz,
                            fp[3 * i + 0], fp[3 * i + 1], fp[3 * i + 2]);
                        unsigned long long pk =
                            ((unsigned long long)k << 32) |
                            (unsigned long long)(unsigned int)i;
                        if (pk <= Pstar)
                            process_point(i, fp, q0x, q0y, q0z, counts);
                    }
                }
        }
        __syncthreads();
    }

    // ---- counts+1 -> L2-normalize*4 -> softmax (warp 0).
    if (t < 32) {
        float c = (float)counts[t] + 1.0f;
        float ss = c * c;
        #pragma unroll
        for (int o = 16; o > 0; o >>= 1) ss += __shfl_xor_sync(0xFFFFFFFFu, ss, o);
        float pip = (c / sqrtf(ss)) * 4.0f;
        float m = pip;
        #pragma unroll
        for (int o = 16; o > 0; o >>= 1)
            m = fmaxf(m, __shfl_xor_sync(0xFFFFFFFFu, m, o));
        float e = expf(pip - m);
        float se = e;
        #pragma unroll
        for (int o = 16; o > 0; o >>= 1) se += __shfl_xor_sync(0xFFFFFFFFu, se, o);
        out[b * PARTS + t] = e / se;
    }
}

extern "C" void kernel_launch(void* const* d_in, const int* in_sizes, int n_in,
                              void* d_out, int out_size)
{
    const float* vp = (const float*)d_in[0];   // sampled_vehicle_points (n_vp, 3)
    const float* fp = (const float*)d_in[1];   // fusion_point          (n_fp, 3)
    float* out = (float*)d_out;                // (n_vp, 32)

    const int n_vp = in_sizes[0] / 3;
    const int n_fp = in_sizes[1] / 3;

    const size_t smem = (size_t)(((n_fp + 3) / 4) * 4);  // digit bytes (20 KB)
    scp_topk_bins_kernel<<<n_vp, NTHREADS, smem>>>(vp, fp, out, n_fp);
}

// round 6
// speedup vs baseline: 1.1004x; 1.1004x over previous
#include <cuda_runtime.h>
#include <math.h>

#define NTHREADS 256
#define NWARPS   (NTHREADS / 32)
#define TOPK_K   200
#define PARTS    32
#define CAND_CAP 1024

// ---------------------------------------------------------------------------
// d^2 with a fixed, non-FMA operation order so every recompute produces
// bit-identical keys.
__device__ __forceinline__ unsigned int key_from(
    float vx, float vy, float vz, float px, float py, float pz)
{
    float dx = __fsub_rn(vx, px);
    float dy = __fsub_rn(vy, py);
    float dz = __fsub_rn(vz, pz);
    float d2 = __fadd_rn(__fadd_rn(__fmul_rn(dx, dx), __fmul_rn(dy, dy)),
                         __fmul_rn(dz, dz));
    return __float_as_uint(d2);   // d2 >= 0, so uint order == float order
}

// Replicates the reference's per-point bin computation for rel = q_j - q_0.
__device__ __forceinline__ void process_point(
    int i, const float* __restrict__ fp,
    float q0x, float q0y, float q0z,
    unsigned int* counts)
{
    const float TWO_PI_F = 6.28318530717958647692f;
    const float PI_F     = 3.14159265358979323846f;

    float rx = __fsub_rn(fp[3 * i + 0], q0x);
    float ry = __fsub_rn(fp[3 * i + 1], q0y);
    float rz = __fsub_rn(fp[3 * i + 2], q0z);

    float axy = fmodf(atan2f(ry, rx) + TWO_PI_F, TWO_PI_F);
    float azy = fmodf(atan2f(ry, rz) + TWO_PI_F, PI_F);
    int xyb = (int)floorf(axy / (TWO_PI_F * 0.25f));
    int zyb = (int)floorf(azy / (PI_F * 0.25f));

    float d2 = __fadd_rn(__fadd_rn(__fmul_rn(rx, rx), __fmul_rn(ry, ry)),
                         __fmul_rn(rz, rz));
    float D = sqrtf(__fadd_rn(d2, 1e-7f));
    int dist = (D >= 4.0f) ? 1 : ((D >= 1.0f) ? 0 : -1);

    if (dist >= 0 && xyb >= 0 && zyb >= 0) {
        int bin = dist * 16 + xyb * 4 + zyb;
        if (bin >= 0 && bin < PARTS) atomicAdd(&counts[bin], 1u);
    }
}

// Parallel "digit where cumulative count reaches `need`" over a 256-bin
// histogram. Warp 0 computes; results broadcast via shared. Also returns the
// count inside the chosen digit (enables early exit in radix select).
__device__ __forceinline__ void find_digit(
    unsigned int* hist, int need, int t,
    unsigned int* s_digit, int* s_need, unsigned int* s_cnt)
{
    if (t < 32) {
        int base = t * 8;
        int s = 0;
        #pragma unroll
        for (int j = 0; j < 8; ++j) s += (int)hist[base + j];
        int cum = s;
        #pragma unroll
        for (int o = 1; o < 32; o <<= 1) {
            int v = __shfl_up_sync(0xFFFFFFFFu, cum, o);
            if (t >= o) cum += v;
        }
        unsigned int bal = __ballot_sync(0xFFFFFFFFu, cum >= need);
        int lane = __ffs(bal) - 1;
        if (t == lane) {
            int c = cum - s;   // exclusive prefix at this lane's first bin
            int d = base;
            while (c + (int)hist[d] < need) { c += (int)hist[d]; ++d; }
            *s_digit = (unsigned int)d;
            *s_need = need - c;
            *s_cnt = hist[d];
        }
    }
    __syncthreads();
}

__global__ __launch_bounds__(NTHREADS)
void scp_topk_bins_kernel(const float* __restrict__ vp,
                          const float* __restrict__ fp,
                          float* __restrict__ out,
                          int n_fp)
{
    __shared__ unsigned int hist[256];
    // During pass A: NWARPS per-warp 256-bin histograms (8 KB).
    // After pass A : candidate array of (key<<32|idx) u64s.
    __shared__ unsigned long long cand[CAND_CAP];
    __shared__ unsigned int counts[PARTS];
    __shared__ unsigned long long minpack;
    __shared__ unsigned int s_cand_count;
    __shared__ unsigned int s_digit;
    __shared__ int s_need;
    __shared__ unsigned int s_cnt;
    extern __shared__ unsigned char digits[];      // one radix digit per point

    unsigned int* const buf32 = (unsigned int*)cand;   // 2048 u32

    const int b = blockIdx.x;
    const int t = threadIdx.x;

    const float vx = vp[3 * b + 0];
    const float vy = vp[3 * b + 1];
    const float vz = vp[3 * b + 2];

    if (t < PARTS) counts[t] = 0;
    if (t == 0) { minpack = ~0ull; s_cand_count = 0; }
    hist[t] = 0;
    #pragma unroll
    for (int j = 0; j < 2048 / NTHREADS; ++j) buf32[j * NTHREADS + t] = 0;
    __syncthreads();

    const int ngroups = n_fp >> 2;
    const int rem = n_fp & 3;
    const int nwords = (n_fp + 3) >> 2;
    const float4* __restrict__ fp4 = (const float4*)fp;
    unsigned int* __restrict__ digw = (unsigned int*)digits;
    unsigned int* const whist = &buf32[(t >> 5) * 256];  // this warp's hist

    // ---- Pass A (only full global scan): keys for 4 points/thread via 3
    // float4 loads; store packed digits; per-warp plain-atomic histogram;
    // scalar 32-bit running min (strict <  ==> lowest index kept per thread).
    unsigned int kmin = 0xFFFFFFFFu;
    unsigned int imin = 0;
    for (int g = t; g < ngroups; g += NTHREADS) {
        float4 A = fp4[g * 3 + 0];
        float4 B = fp4[g * 3 + 1];
        float4 C = fp4[g * 3 + 2];
        unsigned int k0 = key_from(vx, vy, vz, A.x, A.y, A.z);
        unsigned int k1 = key_from(vx, vy, vz, A.w, B.x, B.y);
        unsigned int k2 = key_from(vx, vy, vz, B.z, B.w, C.x);
        unsigned int k3 = key_from(vx, vy, vz, C.y, C.z, C.w);
        digw[g] = (k0 >> 24) | ((k1 >> 24) << 8) |
                  ((k2 >> 24) << 16) | (k3 & 0xFF000000u);

        const unsigned int base = (unsigned int)g * 4u;
        if (k0 < kmin) { kmin = k0; imin = base + 0; }
        if (k1 < kmin) { kmin = k1; imin = base + 1; }
        if (k2 < kmin) { kmin = k2; imin = base + 2; }
        if (k3 < kmin) { kmin = k3; imin = base + 3; }

        atomicAdd(&whist[k0 >> 24], 1u);
        atomicAdd(&whist[k1 >> 24], 1u);
        atomicAdd(&whist[k2 >> 24], 1u);
        atomicAdd(&whist[k3 >> 24], 1u);
    }
    if (rem) {  // tail points + pad digit bytes to the word boundary
        if (t < rem) {
            int i = ngroups * 4 + t;
            unsigned int k = key_from(vx, vy, vz,
                                      fp[3 * i + 0], fp[3 * i + 1], fp[3 * i + 2]);
            digits[i] = (unsigned char)(k >> 24);
            atomicAdd(&whist[k >> 24], 1u);
            if (k < kmin) { kmin = k; imin = (unsigned int)i; }
        } else if (t < 4) {
            digits[ngroups * 4 + t] = 0xFFu;
        }
    }
    // Packed warp-reduce min (lowest index on key ties), one atomic per warp.
    unsigned long long lmin =
        ((unsigned long long)kmin << 32) | (unsigned long long)imin;
    #pragma unroll
    for (int o = 16; o > 0; o >>= 1) {
        unsigned long long v = __shfl_xor_sync(0xFFFFFFFFu, lmin, o);
        if (v < lmin) lmin = v;
    }
    if ((t & 31) == 0) atomicMin(&minpack, lmin);
    __syncthreads();

    // Reduce per-warp histograms into hist[256].
    {
        unsigned int s = 0;
        #pragma unroll
        for (int w = 0; w < NWARPS; ++w) s += buf32[w * 256 + t];
        hist[t] = s;
    }
    __syncthreads();

    find_digit(hist, TOPK_K, t, &s_digit, &s_need, &s_cnt);
    const unsigned int d0 = s_digit;
    const int need = s_need;

    // Anchor = nearest fusion point.
    const unsigned int amin = (unsigned int)(minpack & 0xFFFFFFFFull);
    const float q0x = fp[3 * amin + 0];
    const float q0y = fp[3 * amin + 1];
    const float q0z = fp[3 * amin + 2];

    // ---- Pass B: smem digit scan, SIMD byte classification. (whist data is
    // dead; cand reuses that buffer.)
    const unsigned int d0x4 = d0 * 0x01010101u;
    for (int w = t; w < nwords; w += NTHREADS) {
        unsigned int dw = digw[w];
        unsigned int lt = __vcmpltu4(dw, d0x4);
        unsigned int eq = __vcmpeq4(dw, d0x4);
        if (lt) {
            #pragma unroll
            for (int j = 0; j < 4; ++j)
                if ((lt >> (8 * j)) & 1u)
                    process_point(4 * w + j, fp, q0x, q0y, q0z, counts);
        }
        if (eq) {
            #pragma unroll
            for (int j = 0; j < 4; ++j)
                if ((eq >> (8 * j)) & 1u) {
                    int i = 4 * w + j;
                    if (i < n_fp) {
                        unsigned int k = key_from(vx, vy, vz,
                            fp[3 * i + 0], fp[3 * i + 1], fp[3 * i + 2]);
                        unsigned int p = atomicAdd(&s_cand_count, 1u);
                        if (p < CAND_CAP)
                            cand[p] = ((unsigned long long)k << 32) |
                                      (unsigned long long)(unsigned int)i;
                    }
                }
        }
    }
    __syncthreads();
    const unsigned int nc = s_cand_count;

    if (nc <= CAND_CAP) {
        // ---- Exact need-th smallest packed (key,idx) among candidates via
        // 8-bit radix passes with early exit. Packed ordering reproduces
        // top_k's lowest-index tie-break.
        unsigned long long prefix = (unsigned long long)d0 << 56;
        unsigned long long Pstar = prefix;
        int needc = need;
        for (int pass = 0; pass < 7; ++pass) {
            const int shift = 48 - 8 * pass;
            hist[t] = 0;
            __syncthreads();
            const unsigned long long mask = ~0ull << (shift + 8);
            for (unsigned int j = t; j < nc; j += NTHREADS) {
                unsigned long long pk = cand[j];
                if ((pk & mask) == prefix)
                    atomicAdd(&hist[(unsigned int)(pk >> shift) & 255u], 1u);
            }
            __syncthreads();
            find_digit(hist, needc, t, &s_digit, &s_need, &s_cnt);
            prefix |= (unsigned long long)s_digit << shift;
            needc = s_need;
            if ((int)s_cnt == needc) {  // whole digit taken -> cutoff known
                Pstar = prefix | ((shift > 0) ? ((1ull << shift) - 1ull) : 0ull);
                break;
            }
            if (shift == 0) Pstar = prefix;
        }
        for (unsigned int j = t; j < nc; j += NTHREADS) {
            unsigned long long pk = cand[j];
            if (pk <= Pstar)
                process_point((int)(unsigned int)(pk & 0xFFFFFFFFull),
                              fp, q0x, q0y, q0z, counts);
        }
        __syncthreads();
    } else {
        // ---- Fallback (bucket overflow, statistically never): radix select
        // recomputing candidate keys each pass, filtered by the digit array.
        unsigned long long prefix = (unsigned long long)d0 << 56;
        unsigned long long Pstar = prefix;
        int needc = need;
        for (int pass = 0; pass < 7; ++pass) {
            const int shift = 48 - 8 * pass;
            hist[t] = 0;
            __syncthreads();
            const unsigned long long mask = ~0ull << (shift + 8);
            for (int w = t; w < nwords; w += NTHREADS) {
                unsigned int eq = __vcmpeq4(digw[w], d0x4);
                if (!eq) continue;
                #pragma unroll
                for (int j = 0; j < 4; ++j)
                    if ((eq >> (8 * j)) & 1u) {
                        int i = 4 * w + j;
                        if (i < n_fp) {
                            unsigned int k = key_from(vx, vy, vz,
                                fp[3 * i + 0], fp[3 * i + 1], fp[3 * i + 2]);
                            unsigned long long pk =
                                ((unsigned long long)k << 32) |
                                (unsigned long long)(unsigned int)i;
                            if ((pk & mask) == prefix)
                                atomicAdd(
                                    &hist[(unsigned int)(pk >> shift) & 255u],
                                    1u);
                        }
                    }
            }
            __syncthreads();
            find_digit(hist, needc, t, &s_digit, &s_need, &s_cnt);
            prefix |= (unsigned long long)s_digit << shift;
            needc = s_need;
            if ((int)s_cnt == needc) {
                Pstar = prefix | ((shift > 0) ? ((1ull << shift) - 1ull) : 0ull);
                break;
            }
            if (shift == 0) Pstar = prefix;
        }
        for (int w = t; w < nwords; w += NTHREADS) {
            unsigned int eq = __vcmpeq4(digw[w], d0x4);
            if (!eq) continue;
            #pragma unroll
            for (int j = 0; j < 4; ++j)
                if ((eq >> (8 * j)) & 1u) {
                    int i = 4 * w + j;
                    if (i < n_fp) {
                        unsigned int k = key_from(vx, vy, vz,
                            fp[3 * i + 0], fp[3 * i + 1], fp[3 * i + 2]);
                        unsigned long long pk =
                            ((unsigned long long)k << 32) |
                            (unsigned long long)(unsigned int)i;
                        if (pk <= Pstar)
                            process_point(i, fp, q0x, q0y, q0z, counts);
                    }
                }
        }
        __syncthreads();
    }

    // ---- counts+1 -> L2-normalize*4 -> softmax (warp 0).
    if (t < 32) {
        float c = (float)counts[t] + 1.0f;
        float ss = c * c;
        #pragma unroll
        for (int o = 16; o > 0; o >>= 1) ss += __shfl_xor_sync(0xFFFFFFFFu, ss, o);
        float pip = (c / sqrtf(ss)) * 4.0f;
        float m = pip;
        #pragma unroll
        for (int o = 16; o > 0; o >>= 1)
            m = fmaxf(m, __shfl_xor_sync(0xFFFFFFFFu, m, o));
        float e = expf(pip - m);
        float se = e;
        #pragma unroll
        for (int o = 16; o > 0; o >>= 1) se += __shfl_xor_sync(0xFFFFFFFFu, se, o);
        out[b * PARTS + t] = e / se;
    }
}

extern "C" void kernel_launch(void* const* d_in, const int* in_sizes, int n_in,
                              void* d_out, int out_size)
{
    const float* vp = (const float*)d_in[0];   // sampled_vehicle_points (n_vp, 3)
    const float* fp = (const float*)d_in[1];   // fusion_point          (n_fp, 3)
    float* out = (float*)d_out;                // (n_vp, 32)

    const int n_vp = in_sizes[0] / 3;
    const int n_fp = in_sizes[1] / 3;

    const size_t smem = (size_t)(((n_fp + 3) / 4) * 4);  // digit bytes (~20 KB)
    scp_topk_bins_kernel<<<n_vp, NTHREADS, smem>>>(vp, fp, out, n_fp);
}